// round 15
// baseline (speedup 1.0000x reference)
#include <cuda_runtime.h>

// uDTW forward DP. B=32, N=M=512, alpha=1.
// 16 CTAs x 1024 threads; each CTA processes TWO batches (one per 512-thread
// half). Within a half: 16 warps, 1 row/thread, K=8 diagonals per barrier,
// warps skewed by 8 diags via block index. Half 1 maps warps to row-blocks in
// REVERSE order so the two halves' activity windows anti-align on each SMSP.
// State E = exp(-R); inter-block boundary {E,D} via 32-slot float2 smem ring.
// Final period peeled; SigR computed post-loop from 4 Sig loads.

#define NN     512
#define BB     32
#define KS     8
#define BLKS   16
#define RINGSZ 32
#define PMAIN  142   // main periods 0..141; epilogue = period 142

__global__ __launch_bounds__(1024, 1)
void softdtw_k8(const float* __restrict__ D, const float* __restrict__ Sig,
                float* __restrict__ out) {
    __shared__ float2 ring[2][BLKS][RINGSZ];

    const int t    = threadIdx.x;
    const int half = t >> 9;                    // which batch of the pair
    const int tt   = t & 511;
    const int lane = tt & 31;
    const int w16  = tt >> 5;                   // warp index within half
    const int bi   = half ? (BLKS - 1 - w16) : w16;   // row-block index
    const int batch = 2 * blockIdx.x + half;
    const int r    = 32 * bi + lane + 1;        // matrix row, 1-indexed
    const int rb   = 32 * bi;                   // boundary row feeding this block

    ((float2*)ring)[t] = make_float2(0.f, 0.f); // 2*16*32 = 1024 entries

    const size_t base = (size_t)batch * NN * NN;
    const float* rowD = D + base + (size_t)(r - 1) * NN;
    const bool pub = (lane == 31) && (bi < BLKS - 1);

    // own-row state at diag d-1; carried neighbor-row values at d-1
    float E1 = 0.f, D1 = 0.f;
    float cpE = (bi == 0 && lane == 0) ? 1.f : 0.f;  // E(R[0][0]=0)=1 at d=2
    float cpD = 0.f;

    // col of D value for substep s of period p: 8p + coff + s
    const int coff = -40 * bi - lane;
    float dc[KS], dn[KS];
#pragma unroll
    for (int s = 0; s < KS; ++s) {
        int c = coff + s;
        dc[s] = ((unsigned)c < NN) ? rowD[c] : 0.f;
    }
    __syncthreads();

    const int wlo = 32 * bi + 2;
    const int whi = 32 * bi + 544;

    for (int p = 0; p < PMAIN; ++p) {
        const int dbase = 2 + KS * (p - bi);

        // prefetch next period's D values
#pragma unroll
        for (int s = 0; s < KS; ++s) {
            int c = KS * (p + 1) + coff + s;
            dn[s] = ((unsigned)c < NN) ? rowD[c] : 0.f;
        }

        if (dbase + KS - 1 >= wlo && dbase <= whi) {   // warp-uniform
#pragma unroll
            for (int s = 0; s < KS; ++s) {
                const int d = dbase + s;
                float sE = __shfl_up_sync(0xffffffffu, E1, 1);
                float sD = __shfl_up_sync(0xffffffffu, D1, 1);
                float2 rv = ring[half][bi][(d - 1) & (RINGSZ - 1)];
                bool bvalid = ((unsigned)(d - 2 - rb) < NN);
                float pE1 = (lane == 0) ? (bvalid ? rv.x : 0.f) : sE;
                float pD1 = (lane == 0) ? (bvalid ? rv.y : 0.f) : sD;

                float sum = (cpE + pE1) + E1;
                float iv  = __fdividef(1.f, sum);
                float num = fmaf(E1, D1, fmaf(pE1, pD1, cpE * cpD));
                float nR  = fmaf(num, iv, dc[s]);
                bool v = ((unsigned)(d - r - 1) < NN);
                float En = v ? __expf(-nR) : 0.f;

                cpE = pE1; cpD = pD1;
                E1 = En;  D1 = dc[s];
                if (pub) ring[half][bi + 1][d & (RINGSZ - 1)] = make_float2(E1, D1);
            }
        }

#pragma unroll
        for (int s = 0; s < KS; ++s) dc[s] = dn[s];
        __syncthreads();
    }

    // ---- peeled final period (only block 15 active): capture cell (512,512) ----
    float capE2 = 0.f, capE1c = 0.f, capE0 = 0.f, capR = 0.f;
    {
        const int dbase = 2 + KS * (PMAIN - bi);
        if (dbase + KS - 1 >= wlo && dbase <= whi) {
#pragma unroll
            for (int s = 0; s < KS; ++s) {
                const int d = dbase + s;
                float sE = __shfl_up_sync(0xffffffffu, E1, 1);
                float sD = __shfl_up_sync(0xffffffffu, D1, 1);
                float2 rv = ring[half][bi][(d - 1) & (RINGSZ - 1)];
                bool bvalid = ((unsigned)(d - 2 - rb) < NN);
                float pE1 = (lane == 0) ? (bvalid ? rv.x : 0.f) : sE;
                float pD1 = (lane == 0) ? (bvalid ? rv.y : 0.f) : sD;
                float sum = (cpE + pE1) + E1;
                float iv  = __fdividef(1.f, sum);
                float num = fmaf(E1, D1, fmaf(pE1, pD1, cpE * cpD));
                float nR  = fmaf(num, iv, dc[s]);
                bool v = ((unsigned)(d - r - 1) < NN);
                if (v) { capE2 = cpE; capE1c = pE1; capE0 = E1; capR = nR; }
                float En = v ? __expf(-nR) : 0.f;
                cpE = pE1; cpD = pD1;
                E1 = En;  D1 = dc[s];
            }
        }
    }

    if (r == NN) {   // row 512 of this half's batch (bi==15, lane==31)
        // final cell (512,512): weights {capE2, capE1c, capE0} over
        // Sig preds (511,511), (511,512), (512,511); base Sig(512,512).
        const float* Sg = Sig + base;
        float s00 = Sg[510 * NN + 510];
        float s01 = Sg[510 * NN + 511];
        float s10 = Sg[511 * NN + 510];
        float s11 = Sg[511 * NN + 511];
        float sum = (capE2 + capE1c) + capE0;
        float lastS = s11 + fmaf(capE2, s00, fmaf(capE1c, s01, capE0 * s10)) / sum;
        out[batch]      = capR;    // R[b, N, M]
        out[BB + batch] = lastS;   // SigR[b, N, M]
    }
}

extern "C" void kernel_launch(void* const* d_in, const int* in_sizes, int n_in,
                              void* d_out, int out_size) {
    const float* D   = (const float*)d_in[0];
    const float* Sig = (const float*)d_in[1];
    float* out = (float*)d_out;
    softdtw_k8<<<BB / 2, 1024>>>(D, Sig, out);
}

// round 16
// speedup vs baseline: 1.2358x; 1.2358x over previous
#include <cuda_runtime.h>

// uDTW forward DP. B=32, N=M=512, alpha=1. 32 CTAs x 512 threads, 1 row/thread.
// State E = exp(-R); D stream pre-scaled by -log2(e) so E = ex2(ntilde).
// K=8 diagonals per __syncthreads, 16 warps skewed by 8 diags.
// Ring split: ringE (per-substep STS by lane31) + ringD (written once per
// period, producer D values known at period start). All ring reads and all
// D-shuffles hoisted to period start -> per-substep chain is
// shfl(E) -> SEL -> FADD -> RCP -> FMA -> EX2 -> SEL only.

#define NN     512
#define BB     32
#define KS     8
#define WPS    16
#define RSZ    32
#define PMAIN  142                      // main periods 0..141; peel = 142
#define NL2E  (-1.4426950408889634f)    // -log2(e)
#define NLN2  (-0.6931471805599453f)    // -ln(2)

__device__ __forceinline__ float frcp(float x) {
    float r; asm("rcp.approx.f32 %0, %1;" : "=f"(r) : "f"(x)); return r;
}
__device__ __forceinline__ float fex2(float x) {
    float r; asm("ex2.approx.f32 %0, %1;" : "=f"(r) : "f"(x)); return r;
}

__global__ __launch_bounds__(512, 1)
void softdtw_k9(const float* __restrict__ D, const float* __restrict__ Sig,
                float* __restrict__ out) {
    __shared__ float ringE[WPS][RSZ];
    __shared__ float ringD[WPS][RSZ];

    const int b    = blockIdx.x;
    const int t    = threadIdx.x;
    const int lane = t & 31;
    const int w    = t >> 5;
    const int r    = t + 1;            // matrix row, 1-indexed
    const int rb   = 32 * w;           // boundary row feeding this warp

    ((float*)ringE)[t] = 0.f;          // 16*32 = 512 entries each
    ((float*)ringD)[t] = 0.f;

    const size_t base = (size_t)b * NN * NN;
    const float* rowD = D + base + (size_t)t * NN;
    const bool pub = (lane == 31) && (w < WPS - 1);
    const int coff = -40 * w - lane;   // col of dct[s] at period p: 8p+coff+s

    // own-row state at diag d-1; carried neighbor values at d-1
    float E1 = 0.f, D1t = 0.f;
    float cpE = (t == 0) ? 1.f : 0.f;  // sentinel: E(R[0][0]=0)=1 enters at d=2
    float cpDt = 0.f;
    float pdCarry = 0.f;               // shfl of prev period's dct[7]

    float dct[KS], dnt[KS];
#pragma unroll
    for (int s = 0; s < KS; ++s) {
        int c = coff + s;
        dct[s] = ((unsigned)c < NN) ? NL2E * rowD[c] : 0.f;
    }
    __syncthreads();

    const int wlo = 32 * w + 2;
    const int whi = 32 * w + 544;

    for (int p = 0; p < PMAIN; ++p) {
        const int dbase = 2 + KS * (p - w);

        // prefetch next period's (pre-scaled) D values
#pragma unroll
        for (int s = 0; s < KS; ++s) {
            int c = KS * (p + 1) + coff + s;
            dnt[s] = ((unsigned)c < NN) ? NL2E * rowD[c] : 0.f;
        }
        // hoisted ring reads (slots disjoint from this period's ring writes)
        float rvE[KS], rvD[KS];
#pragma unroll
        for (int s = 0; s < KS; ++s) {
            int slot = (dbase + s - 1) & (RSZ - 1);
            rvE[s] = ringE[w][slot];
            rvD[s] = ringD[w][slot];
        }
        // hoisted D shuffles: neighbor-row D at diag dbase+s-1
        float pD[KS];
        {
            float shD[KS];
#pragma unroll
            for (int s = 0; s < KS; ++s) shD[s] = __shfl_up_sync(0xffffffffu, dct[s], 1);
            pD[0] = pdCarry;
#pragma unroll
            for (int s = 1; s < KS; ++s) pD[s] = shD[s - 1];
            pdCarry = shD[KS - 1];
        }
        // producer publishes its whole period's D values up-front
        if (pub) {
#pragma unroll
            for (int s = 0; s < KS; ++s)
                ringD[w + 1][(dbase + s) & (RSZ - 1)] = dct[s];
        }

        if (dbase + KS - 1 >= wlo && dbase <= whi) {   // warp-uniform
#pragma unroll
            for (int s = 0; s < KS; ++s) {
                const int d = dbase + s;
                float shE = __shfl_up_sync(0xffffffffu, E1, 1);
                bool bvalid = ((unsigned)(d - 2 - rb) < NN);
                float pE1 = (lane == 0) ? (bvalid ? rvE[s] : 0.f) : shE;
                float pD1 = (lane == 0) ? (bvalid ? rvD[s] : 0.f) : pD[s];

                float sum = (cpE + pE1) + E1;
                float iv  = frcp(sum);
                float num = fmaf(E1, D1t, fmaf(pE1, pD1, cpE * cpDt));
                float nt  = fmaf(num, iv, dct[s]);       // -log2e * R
                bool v = ((unsigned)(d - r - 1) < NN);
                float En = v ? fex2(nt) : 0.f;

                cpE = pE1; cpDt = pD1;
                E1 = En;  D1t = dct[s];
                if (pub) ringE[w + 1][d & (RSZ - 1)] = En;
            }
        }

#pragma unroll
        for (int s = 0; s < KS; ++s) dct[s] = dnt[s];
        __syncthreads();
    }

    // ---- peeled final period (only warp 15 active): capture cell (512,512) ----
    float capE2 = 0.f, capE1v = 0.f, capE0 = 0.f, capN = 0.f;
    {
        const int dbase = 2 + KS * (PMAIN - w);
        float rvE[KS], rvD[KS];
#pragma unroll
        for (int s = 0; s < KS; ++s) {
            int slot = (dbase + s - 1) & (RSZ - 1);
            rvE[s] = ringE[w][slot];
            rvD[s] = ringD[w][slot];
        }
        float pD[KS];
        {
            float shD[KS];
#pragma unroll
            for (int s = 0; s < KS; ++s) shD[s] = __shfl_up_sync(0xffffffffu, dct[s], 1);
            pD[0] = pdCarry;
#pragma unroll
            for (int s = 1; s < KS; ++s) pD[s] = shD[s - 1];
        }
        if (dbase + KS - 1 >= wlo && dbase <= whi) {
#pragma unroll
            for (int s = 0; s < KS; ++s) {
                const int d = dbase + s;
                float shE = __shfl_up_sync(0xffffffffu, E1, 1);
                bool bvalid = ((unsigned)(d - 2 - rb) < NN);
                float pE1 = (lane == 0) ? (bvalid ? rvE[s] : 0.f) : shE;
                float pD1 = (lane == 0) ? (bvalid ? rvD[s] : 0.f) : pD[s];

                float sum = (cpE + pE1) + E1;
                float iv  = frcp(sum);
                float num = fmaf(E1, D1t, fmaf(pE1, pD1, cpE * cpDt));
                float nt  = fmaf(num, iv, dct[s]);
                bool v = ((unsigned)(d - r - 1) < NN);
                if (v) { capE2 = cpE; capE1v = pE1; capE0 = E1; capN = nt; }
                float En = v ? fex2(nt) : 0.f;
                cpE = pE1; cpDt = pD1;
                E1 = En;  D1t = dct[s];
            }
        }
    }

    if (t == NN - 1) {   // row 512: final cell (512,512) captured at d=1024
        const float* Sg = Sig + base;
        float s00 = Sg[510 * NN + 510];
        float s01 = Sg[510 * NN + 511];
        float s10 = Sg[511 * NN + 510];
        float s11 = Sg[511 * NN + 511];
        float sum = (capE2 + capE1v) + capE0;
        float lastS = s11 + fmaf(capE2, s00, fmaf(capE1v, s01, capE0 * s10)) / sum;
        out[b]      = capN * NLN2;   // recover R from -log2e * R
        out[BB + b] = lastS;
    }
}

extern "C" void kernel_launch(void* const* d_in, const int* in_sizes, int n_in,
                              void* d_out, int out_size) {
    const float* D   = (const float*)d_in[0];
    const float* Sig = (const float*)d_in[1];
    float* out = (float*)d_out;
    softdtw_k9<<<BB, 512>>>(D, Sig, out);
}